// round 3
// baseline (speedup 1.0000x reference)
#include <cuda_runtime.h>

#define NN   100000
#define EE   800000
#define D    64
#define CD   256          // (HOPS+1)*D
#define NG   64
#define EMBD 128
#define PB   512          // prep blocks (must be co-resident: 148 SMs * 4)
#define CH   196          // nodes per prep block (512*196 >= NN)

// Persistent scratch
__device__ float d_F[(size_t)NN * CD];   // concat features [N][256]
__device__ int   d_cnt[NN];
__device__ int   d_cur[NN];
__device__ int   d_off[NN + 1];
__device__ int   d_csr[EE];
__device__ int   d_bsum[PB];
__device__ float d_dn[NN];
__device__ float d_gsum[NG * D];
__device__ int   d_bar_cnt = 0;
__device__ int   d_bar_gen = 0;

// ---------------------------------------------------------------------------
// Packed fp32x2 (Blackwell FFMA2)
__device__ __forceinline__ unsigned long long pk2(float x, float y) {
    unsigned long long r;
    asm("mov.b64 %0, {%1,%2};" : "=l"(r) : "f"(x), "f"(y));
    return r;
}
__device__ __forceinline__ void upk2(unsigned long long v, float& lo, float& hi) {
    asm("mov.b64 {%0,%1}, %2;" : "=f"(lo), "=f"(hi) : "l"(v));
}
__device__ __forceinline__ void ffma2(unsigned long long& d, unsigned long long a,
                                      unsigned long long b) {
    asm("fma.rn.f32x2 %0, %1, %2, %0;" : "+l"(d) : "l"(a), "l"(b));
}

// ---------------------------------------------------------------------------
// Software grid barrier (all PB blocks co-resident by construction)
__device__ __forceinline__ void gbar() {
    __threadfence();
    __syncthreads();
    if (threadIdx.x == 0) {
        int g = *((volatile int*)&d_bar_gen);
        int r = atomicAdd(&d_bar_cnt, 1);
        if (r == PB - 1) {
            d_bar_cnt = 0;
            __threadfence();
            atomicAdd(&d_bar_gen, 1);
        } else {
            while (*((volatile int*)&d_bar_gen) == g) {}
        }
    }
    __syncthreads();
}

// Fused preprocessing: zero -> count -> scan(off,dn) + copy h -> CSR fill
__global__ void __launch_bounds__(256, 4) k_prep(const float* __restrict__ h,
                                                 const int* __restrict__ src,
                                                 const int* __restrict__ dst) {
    __shared__ int sh[256];
    int tid = threadIdx.x, b = blockIdx.x;
    int gt = b * 256 + tid;
    const int GS = PB * 256;

    // P0: zero counters + gsum
    for (int i = gt; i < NN; i += GS) { d_cnt[i] = 0; d_cur[i] = 0; }
    for (int i = gt; i < NG * D; i += GS) d_gsum[i] = 0.f;
    gbar();

    // P1: in-degree count + copy h into F slot0
    for (int e = gt; e < EE; e += GS) atomicAdd(&d_cnt[dst[e]], 1);
    for (int i = gt; i < NN * 16; i += GS) {
        int r = i >> 4, p = i & 15;
        ((float4*)d_F)[(size_t)r * 64 + p] = ((const float4*)h)[i];
    }
    gbar();

    // P2: per-block chunk sums
    {
        int i0 = b * CH;
        int v = 0;
        if (tid < CH && i0 + tid < NN) v = d_cnt[i0 + tid];
        sh[tid] = v;
        __syncthreads();
        for (int st = 128; st > 0; st >>= 1) {
            if (tid < st) sh[tid] += sh[tid + st];
            __syncthreads();
        }
        if (tid == 0) d_bsum[b] = sh[0];
    }
    gbar();

    // P3: exclusive prefix (off) + deg_norm
    {
        int part = 0;
        for (int i = tid; i < b; i += 256) part += d_bsum[i];
        sh[tid] = part;
        __syncthreads();
        for (int st = 128; st > 0; st >>= 1) {
            if (tid < st) sh[tid] += sh[tid + st];
            __syncthreads();
        }
        int base = sh[0];
        __syncthreads();

        int i0 = b * CH, idx = i0 + tid;
        int v = (tid < CH && idx < NN) ? d_cnt[idx] : 0;
        sh[tid] = v;
        __syncthreads();
        for (int st = 1; st < 256; st <<= 1) {           // inclusive scan
            int a = (tid >= st) ? sh[tid - st] : 0;
            __syncthreads();
            sh[tid] += a;
            __syncthreads();
        }
        if (tid < CH && idx < NN) {
            d_off[idx] = base + sh[tid] - v;
            d_dn[idx] = rsqrtf(fmaxf((float)v, 1.0f));
        }
        if (gt == 0) d_off[NN] = EE;
    }
    gbar();

    // P4: CSR fill
    for (int e = gt; e < EE; e += GS) {
        int dd = dst[e];
        int p = atomicAdd(&d_cur[dd], 1);
        d_csr[d_off[dd] + p] = src[e];
    }
}

// ---------------------------------------------------------------------------
// Hop: half-warp (16 lanes x float4) per node.
// F[n][hop*64+:] = dn[n] * sum_{e in in(n)} dn[s] * F[s][(hop-1)*64+:]
__global__ void __launch_bounds__(256) k_hop(int hop) {
    int node = blockIdx.x * 16 + (threadIdx.x >> 4);    // grid 6250*16 == NN
    int lane = threadIdx.x & 15;
    int e0 = __ldg(d_off + node);
    int e1 = __ldg(d_off + node + 1);
    const float4* F4 = (const float4*)d_F;
    int slot_in = (hop - 1) * 16 + lane;
    float4 acc = make_float4(0.f, 0.f, 0.f, 0.f);
    int s = 0; float w = 0.f;
    if (e0 < e1) { s = __ldg(d_csr + e0); w = __ldg(d_dn + s); }
    for (int e = e0; e < e1; e++) {
        int sn = 0; float wn = 0.f;
        if (e + 1 < e1) { sn = __ldg(d_csr + e + 1); wn = __ldg(d_dn + sn); }
        float4 v = __ldg(F4 + (size_t)s * 64 + slot_in);
        acc.x = fmaf(v.x, w, acc.x);
        acc.y = fmaf(v.y, w, acc.y);
        acc.z = fmaf(v.z, w, acc.z);
        acc.w = fmaf(v.w, w, acc.w);
        s = sn; w = wn;
    }
    float dn = __ldg(d_dn + node);
    acc.x *= dn; acc.y *= dn; acc.z *= dn; acc.w *= dn;
    ((float4*)d_F)[(size_t)node * 64 + hop * 16 + lane] = acc;
}

// ---------------------------------------------------------------------------
// GEMM: one thread per node row. W chunk in smem; packed W pairs come directly
// from ulonglong2 smem loads (no packing MOVs). FFMA2-pipe bound.
// out[n][c] = relu(F[n][0:256] @ W + b)  -> F slot0 (in-place safe per-thread)
__global__ void __launch_bounds__(128) k_gemm(const float* __restrict__ W,
                                              const float* __restrict__ b) {
    __shared__ float Ws[128 * 64];     // 32KB: half of W (128 k-rows x 64 cols)
    int tid = threadIdx.x;
    int n = blockIdx.x * 128 + tid;
    bool ok = (n < NN);
    const float4* xrow = (const float4*)(d_F + (size_t)n * CD);

    unsigned long long acc[32];
#pragma unroll
    for (int p = 0; p < 32; p++) acc[p] = 0ull;

    for (int kc = 0; kc < 2; kc++) {
        __syncthreads();
        for (int i = tid; i < 2048; i += 128)
            ((float4*)Ws)[i] = __ldg((const float4*)W + kc * 2048 + i);
        __syncthreads();

        float4 xv = ok ? __ldg(xrow + kc * 32) : make_float4(0.f, 0.f, 0.f, 0.f);
        for (int j4 = 0; j4 < 32; j4++) {
            float4 xn = (j4 < 31 && ok) ? __ldg(xrow + kc * 32 + j4 + 1) : xv;
#pragma unroll
            for (int jj = 0; jj < 4; jj++) {
                float x = (jj == 0) ? xv.x : (jj == 1) ? xv.y : (jj == 2) ? xv.z : xv.w;
                unsigned long long xp = pk2(x, x);
                const ulonglong2* wr = (const ulonglong2*)(Ws + (j4 * 4 + jj) * 64);
#pragma unroll
                for (int c = 0; c < 16; c++) {
                    ulonglong2 wv = wr[c];   // LDS.128 uniform -> 2 packed pairs
                    ffma2(acc[2 * c + 0], xp, wv.x);
                    ffma2(acc[2 * c + 1], xp, wv.y);
                }
            }
            xv = xn;
        }
    }

    if (ok) {
        float* orow = d_F + (size_t)n * CD;
#pragma unroll
        for (int c4 = 0; c4 < 16; c4++) {
            float4 bv = __ldg((const float4*)b + c4);
            float o0, o1, o2, o3;
            upk2(acc[2 * c4 + 0], o0, o1);
            upk2(acc[2 * c4 + 1], o2, o3);
            float4 o;
            o.x = fmaxf(o0 + bv.x, 0.f);
            o.y = fmaxf(o1 + bv.y, 0.f);
            o.z = fmaxf(o2 + bv.z, 0.f);
            o.w = fmaxf(o3 + bv.w, 0.f);
            ((float4*)orow)[c4] = o;
        }
    }
}

// ---------------------------------------------------------------------------
// Per-graph sums of F slot0 (graph_ids sorted -> running-accumulator flush)
__global__ void k_gsum(const int* __restrict__ gid) {
    const int CHN = 512;
    int c = threadIdx.x & 63;
    int r0 = threadIdx.x >> 6;
    int nbeg = blockIdx.x * CHN + r0;
    int nend = min(NN, blockIdx.x * CHN + CHN);
    float acc = 0.f;
    int cur = -1;
    for (int n = nbeg; n < nend; n += 4) {
        int g = gid[n];
        if (g != cur) {
            if (cur >= 0) atomicAdd(&d_gsum[cur * D + c], acc);
            cur = g; acc = 0.f;
        }
        acc += d_F[(size_t)n * CD + c];
    }
    if (cur >= 0) atomicAdd(&d_gsum[cur * D + c], acc);
}

// Readout: mean -> @embW + embb -> L2 normalize.
__global__ void k_final(const int* __restrict__ gid,
                        const float* __restrict__ embW,
                        const float* __restrict__ embb,
                        float* __restrict__ out) {
    __shared__ float hg[NG][D];
    __shared__ int bnd[NG + 1];
    __shared__ float nrm[NG];
    int tid = threadIdx.x;

    if (tid <= NG) {
        int lo = 0, hi = NN;
        while (lo < hi) {
            int mid = (lo + hi) >> 1;
            if (gid[mid] < tid) lo = mid + 1; else hi = mid;
        }
        bnd[tid] = lo;
    }
    if (tid < NG) nrm[tid] = 0.f;
    __syncthreads();

    for (int idx = tid; idx < NG * D; idx += 128) {
        int g = idx >> 6;
        float cnt = (float)max(bnd[g + 1] - bnd[g], 1);
        hg[g][idx & 63] = d_gsum[idx] / cnt;
    }
    __syncthreads();

    for (int idx = tid; idx < NG * EMBD; idx += 128) {
        int g = idx >> 7, e = idx & 127;
        float s = embb[e];
#pragma unroll 16
        for (int k = 0; k < D; k++) s += hg[g][k] * embW[k * EMBD + e];
        atomicAdd(&nrm[g], s * s);
    }
    __syncthreads();

    for (int idx = tid; idx < NG * EMBD; idx += 128) {
        int g = idx >> 7, e = idx & 127;
        float s = embb[e];
#pragma unroll 16
        for (int k = 0; k < D; k++) s += hg[g][k] * embW[k * EMBD + e];
        float nv = fmaxf(sqrtf(nrm[g]), 1e-12f);
        out[idx] = s / nv;
    }
}

// ---------------------------------------------------------------------------
extern "C" void kernel_launch(void* const* d_in, const int* in_sizes, int n_in,
                              void* d_out, int out_size) {
    const float* h    = (const float*)d_in[0];
    const int*   src  = (const int*)d_in[1];
    const int*   dst  = (const int*)d_in[2];
    const int*   gid  = (const int*)d_in[3];
    const float* Wl[3] = {(const float*)d_in[4], (const float*)d_in[6], (const float*)d_in[8]};
    const float* bl[3] = {(const float*)d_in[5], (const float*)d_in[7], (const float*)d_in[9]};
    const float* embW = (const float*)d_in[10];
    const float* embb = (const float*)d_in[11];
    float* out = (float*)d_out;
    (void)in_sizes; (void)n_in; (void)out_size;

    k_prep<<<PB, 256>>>(h, src, dst);                    // launch 1

    for (int L = 0; L < 3; L++) {
        k_hop<<<NN / 16, 256>>>(1);                      // launches 2,3,4 in layer 0
        k_hop<<<NN / 16, 256>>>(2);
        k_hop<<<NN / 16, 256>>>(3);
        k_gemm<<<(NN + 127) / 128, 128>>>(Wl[L], bl[L]);
    }

    k_gsum<<<(NN + 511) / 512, 256>>>(gid);
    k_final<<<1, 128>>>(gid, embW, embb, out);
}